// round 12
// baseline (speedup 1.0000x reference)
#include <cuda_runtime.h>
#include <cstdint>

// Problem constants (fixed by the dataset: V=8192 vertices, E=40000 tets)
#define V 8192
#define E 40000
#define E_BLOCKS ((E + 255) / 256)
#define ROWS_PER_TILE 4
#define MV_TILES (V / ROWS_PER_TILE)     // 2048 tiles
#define MV_BLOCKS (148 * 5)              // one full wave at 5 blocks/SM

// Scratch (device globals — no allocations allowed). 16B-aligned for float4 LDG.
__device__ __align__(16) float g_dx[V];
__device__ __align__(16) float g_dy[V];
__device__ __align__(16) float g_dz[V];
__device__ double g_kin_accum;     // sum_i delta_i . (M delta)_i   (atomic)
__device__ double g_el_accum;      // sum_e psi_e * measure_e       (atomic)
__device__ unsigned int g_steal;   // tile work-stealing counter
__device__ unsigned int g_done;    // matvec block completion counter

// ---------------------------------------------------------------------------
// Kernel 1 (fused prologue): elastic energy per element + delta computation.
//   first V threads: delta = next_pos - (pos + vel*dt + ext*dt^2)  (SoA)
//   all e < E:       psi(F(e)) * measure[e][3][0], block-reduced + atomic
// elements is int32 on device (JAX x64 disabled); clamped defensively.
// ---------------------------------------------------------------------------
__global__ __launch_bounds__(256) void prologue_kernel(
    const float* __restrict__ next_pos,
    const float* __restrict__ pos,
    const float* __restrict__ vel,
    const float* __restrict__ ext,
    const float* __restrict__ ts_ptr,
    const int* __restrict__ elems,
    const float* __restrict__ poly,
    const float* __restrict__ measure,
    const float* __restrict__ lam,
    const float* __restrict__ mu)
{
    int gid = blockIdx.x * blockDim.x + threadIdx.x;

    if (gid == 0) {
        g_kin_accum = 0.0;
        g_el_accum  = 0.0;
        g_steal     = 0u;
        g_done      = 0u;
    }

    // --- delta part (first V threads) ---
    if (gid < V) {
        float dt  = ts_ptr[0];
        float dt2 = dt * dt;
        int b = gid * 3;
        g_dx[gid] = next_pos[b + 0] - (pos[b + 0] + vel[b + 0] * dt + ext[b + 0] * dt2);
        g_dy[gid] = next_pos[b + 1] - (pos[b + 1] + vel[b + 1] * dt + ext[b + 1] * dt2);
        g_dz[gid] = next_pos[b + 2] - (pos[b + 2] + vel[b + 2] * dt + ext[b + 2] * dt2);
    }

    // --- elastic part ---
    float val = 0.f;
    if (gid < E) {
        int e = gid;
        float F00 = 0.f, F01 = 0.f, F02 = 0.f;
        float F10 = 0.f, F11 = 0.f, F12 = 0.f;
        float F20 = 0.f, F21 = 0.f, F22 = 0.f;
        const int4 ev = reinterpret_cast<const int4*>(elems)[e];
        int vidx[4] = { ev.x, ev.y, ev.z, ev.w };
        const float4* __restrict__ pl4 = reinterpret_cast<const float4*>(poly) + (size_t)e * 4;
#pragma unroll
        for (int f = 0; f < 4; ++f) {
            int vi = vidx[f];
            vi = vi < 0 ? 0 : (vi >= V ? V - 1 : vi);   // defensive clamp
            const float* p = next_pos + (size_t)vi * 3;
            float px = p[0], py = p[1], pz = p[2];
            float4 pl = pl4[f];
            float p0 = pl.x, p1 = pl.y, p2 = pl.z;
            F00 += px * p0; F01 += px * p1; F02 += px * p2;
            F10 += py * p0; F11 += py * p1; F12 += py * p2;
            F20 += pz * p0; F21 += pz * p1; F22 += pz * p2;
        }
        float Ic = F00*F00 + F01*F01 + F02*F02
                 + F10*F10 + F11*F11 + F12*F12
                 + F20*F20 + F21*F21 + F22*F22;
        float J = F00 * (F11 * F22 - F12 * F21)
                - F01 * (F10 * F22 - F12 * F20)
                + F02 * (F10 * F21 - F11 * F20);
        float l = lam[e], m = mu[e];
        float alpha = 0.75f * m / l + 1.0f;
        float Icv = fmaxf(Ic + 1.0f, 0.0f);
        float d = J - alpha;
        float psi = 0.5f * m * (Ic - 3.0f)
                  + 0.5f * l * d * d
                  - 0.5f * m * logf(Icv + 1e-30f);
        val = psi * measure[(size_t)e * 4 + 3];
    }

#pragma unroll
    for (int off = 16; off > 0; off >>= 1)
        val += __shfl_down_sync(0xFFFFFFFFu, val, off);
    __shared__ float sh[8];
    int lane = threadIdx.x & 31;
    int warp = threadIdx.x >> 5;
    if (lane == 0) sh[warp] = val;
    __syncthreads();
    if (threadIdx.x == 0) {
        float s = 0.f;
#pragma unroll
        for (int w = 0; w < 8; ++w) s += sh[w];
        atomicAdd(&g_el_accum, (double)s);
    }
}

// ---------------------------------------------------------------------------
// Kernel 2: persistent matvec. One full wave of blocks (740 = 148 SM x 5);
// blocks steal 4-row tiles until all 2048 are consumed -> no wave
// quantization, no tail. Per tile each thread folds its 12 column-partials
// into a per-thread double using the delta[row] weights (broadcast loads),
// so the block reduces + atomics exactly once at the end.
// M streamed with __ldcs; inner loop is the measured-best R11 shape.
// ---------------------------------------------------------------------------
__global__ __launch_bounds__(256, 5) void matvec_kernel(const float* __restrict__ M,
                                                        const float* __restrict__ ts_ptr,
                                                        float* __restrict__ out)
{
    const float4* __restrict__ DX = reinterpret_cast<const float4*>(g_dx);
    const float4* __restrict__ DY = reinterpret_cast<const float4*>(g_dy);
    const float4* __restrict__ DZ = reinterpret_cast<const float4*>(g_dz);

    __shared__ unsigned int sh_tile;
    __shared__ double shd[8];

    double tacc = 0.0;   // per-thread running contribution across tiles

    for (;;) {
        if (threadIdx.x == 0)
            sh_tile = atomicAdd(&g_steal, 1u);
        __syncthreads();
        unsigned int tile = sh_tile;
        __syncthreads();
        if (tile >= MV_TILES) break;

        const int row0 = tile * ROWS_PER_TILE;
        const float4* __restrict__ M0 = reinterpret_cast<const float4*>(M + (size_t)(row0 + 0) * V);
        const float4* __restrict__ M1 = reinterpret_cast<const float4*>(M + (size_t)(row0 + 1) * V);
        const float4* __restrict__ M2 = reinterpret_cast<const float4*>(M + (size_t)(row0 + 2) * V);
        const float4* __restrict__ M3 = reinterpret_cast<const float4*>(M + (size_t)(row0 + 3) * V);

        float a00=0.f,a01=0.f,a02=0.f, a10=0.f,a11=0.f,a12=0.f;
        float a20=0.f,a21=0.f,a22=0.f, a30=0.f,a31=0.f,a32=0.f;

#pragma unroll
        for (int it = 0; it < (V / 4) / 256; ++it) {
            int idx = threadIdx.x + it * 256;
            float4 m0 = __ldcs(&M0[idx]);
            float4 m1 = __ldcs(&M1[idx]);
            float4 m2 = __ldcs(&M2[idx]);
            float4 m3 = __ldcs(&M3[idx]);
            float4 x  = DX[idx];
            float4 y  = DY[idx];
            float4 z  = DZ[idx];

            a00 += m0.x*x.x + m0.y*x.y + m0.z*x.z + m0.w*x.w;
            a01 += m0.x*y.x + m0.y*y.y + m0.z*y.z + m0.w*y.w;
            a02 += m0.x*z.x + m0.y*z.y + m0.z*z.z + m0.w*z.w;

            a10 += m1.x*x.x + m1.y*x.y + m1.z*x.z + m1.w*x.w;
            a11 += m1.x*y.x + m1.y*y.y + m1.z*y.z + m1.w*y.w;
            a12 += m1.x*z.x + m1.y*z.y + m1.z*z.z + m1.w*z.w;

            a20 += m2.x*x.x + m2.y*x.y + m2.z*x.z + m2.w*x.w;
            a21 += m2.x*y.x + m2.y*y.y + m2.z*y.z + m2.w*y.w;
            a22 += m2.x*z.x + m2.y*z.y + m2.z*z.z + m2.w*z.w;

            a30 += m3.x*x.x + m3.y*x.y + m3.z*x.z + m3.w*x.w;
            a31 += m3.x*y.x + m3.y*y.y + m3.z*y.z + m3.w*y.w;
            a32 += m3.x*z.x + m3.y*z.y + m3.z*z.z + m3.w*z.w;
        }

        // fold this tile's partials into the per-thread accumulator using
        // the delta[row] weights (uniform broadcast loads, L1-resident)
        float c = 0.f;
        c += g_dx[row0 + 0] * a00 + g_dy[row0 + 0] * a01 + g_dz[row0 + 0] * a02;
        c += g_dx[row0 + 1] * a10 + g_dy[row0 + 1] * a11 + g_dz[row0 + 1] * a12;
        c += g_dx[row0 + 2] * a20 + g_dy[row0 + 2] * a21 + g_dz[row0 + 2] * a22;
        c += g_dx[row0 + 3] * a30 + g_dy[row0 + 3] * a31 + g_dz[row0 + 3] * a32;
        tacc += (double)c;
    }

    // single end-of-block reduction of the per-thread doubles
#pragma unroll
    for (int off = 16; off > 0; off >>= 1)
        tacc += __shfl_down_sync(0xFFFFFFFFu, tacc, off);
    int lane = threadIdx.x & 31;
    int warp = threadIdx.x >> 5;
    if (lane == 0) shd[warp] = tacc;
    __syncthreads();

    if (threadIdx.x == 0) {
        double s = 0.0;
#pragma unroll
        for (int w = 0; w < 8; ++w) s += shd[w];
        atomicAdd(&g_kin_accum, s);

        __threadfence();
        unsigned int t = atomicAdd(&g_done, 1u);
        if (t == (unsigned int)(MV_BLOCKS - 1)) {
            // all kinetic atomics visible; elastic finished (stream order)
            double dt = (double)ts_ptr[0];
            double inv_h = 1.0 / dt;
            double coeff = inv_h * inv_h * 0.5;
            double kin = coeff * g_kin_accum;
            double el  = g_el_accum;
            out[0] = (float)(kin + el);
            out[1] = (float)kin;
            out[2] = (float)el;
        }
    }
}

// ---------------------------------------------------------------------------
// Launch
// ---------------------------------------------------------------------------
extern "C" void kernel_launch(void* const* d_in, const int* in_sizes, int n_in,
                              void* d_out, int out_size)
{
    const float* next_pos = (const float*)d_in[0];
    const float* pos      = (const float*)d_in[1];
    const float* vel      = (const float*)d_in[2];
    const float* ext      = (const float*)d_in[3];
    const float* M        = (const float*)d_in[4];
    const int*   elems    = (const int*)d_in[5];
    const float* poly     = (const float*)d_in[6];
    const float* measure  = (const float*)d_in[7];
    const float* lam      = (const float*)d_in[8];
    const float* mu       = (const float*)d_in[9];
    const float* ts       = (const float*)d_in[10];
    float* out = (float*)d_out;

    prologue_kernel<<<E_BLOCKS, 256>>>(next_pos, pos, vel, ext, ts,
                                       elems, poly, measure, lam, mu);
    matvec_kernel<<<MV_BLOCKS, 256>>>(M, ts, out);
}